// round 3
// baseline (speedup 1.0000x reference)
#include <cuda_runtime.h>

// CrossLayer DCN, closed form:
//   t_l = <x, W_l>  (3 independent dots, one pass)
//   s1 = 1 + t1
//   s2 = s1 + (s1*t2 + c2),   c2 = <b1, W2>
//   s3 = s2 + (s2*t3 + c3),   c3 = <b1+b2, W3>
//   out = x * s3 + (b1+b2+b3)
// Prologue (1 block) computes c2, c3, bsum once; main kernel does one
// reduction per row instead of three serial layer reductions.

#define D 1024
#define DV (D / 4)      // 256 float4 per row
#define L 3
#define THREADS 256
#define G 8

__device__ float4 g_bsum[DV];
__device__ float  g_c[2];

__global__ __launch_bounds__(THREADS)
void prologue_kernel(const float4* __restrict__ W4,
                     const float4* __restrict__ b4)
{
    const int tid  = threadIdx.x;
    const int lane = tid & 31;
    const int wid  = tid >> 5;

    float4 b1 = b4[tid];
    float4 b2 = b4[DV + tid];
    float4 b3 = b4[2 * DV + tid];
    float4 w2 = W4[DV + tid];
    float4 w3 = W4[2 * DV + tid];

    float4 bs;
    bs.x = b1.x + b2.x + b3.x;
    bs.y = b1.y + b2.y + b3.y;
    bs.z = b1.z + b2.z + b3.z;
    bs.w = b1.w + b2.w + b3.w;
    g_bsum[tid] = bs;

    float p2 = b1.x * w2.x + b1.y * w2.y + b1.z * w2.z + b1.w * w2.w;
    float4 b12;
    b12.x = b1.x + b2.x; b12.y = b1.y + b2.y;
    b12.z = b1.z + b2.z; b12.w = b1.w + b2.w;
    float p3 = b12.x * w3.x + b12.y * w3.y + b12.z * w3.z + b12.w * w3.w;

    #pragma unroll
    for (int o = 16; o > 0; o >>= 1) {
        p2 += __shfl_xor_sync(0xFFFFFFFFu, p2, o);
        p3 += __shfl_xor_sync(0xFFFFFFFFu, p3, o);
    }

    __shared__ float r2[8], r3[8];
    if (lane == 0) { r2[wid] = p2; r3[wid] = p3; }
    __syncthreads();
    if (tid == 0) {
        float c2 = 0.f, c3 = 0.f;
        #pragma unroll
        for (int i = 0; i < 8; i++) { c2 += r2[i]; c3 += r3[i]; }
        g_c[0] = c2;
        g_c[1] = c3;
    }
}

__global__ __launch_bounds__(THREADS)
void cross_layer_kernel(const float4* __restrict__ x4,
                        const float4* __restrict__ W4,
                        float4* __restrict__ out4)
{
    const int tid  = threadIdx.x;
    const int lane = tid & 31;
    const int wid  = tid >> 5;

    __shared__ float4 red[2][8];

    // W register-resident across all G rows (12 regs)
    const float4 w1 = __ldg(&W4[tid]);
    const float4 w2 = __ldg(&W4[DV + tid]);
    const float4 w3 = __ldg(&W4[2 * DV + tid]);
    const float4 bs = g_bsum[tid];
    const float  c2 = g_c[0];
    const float  c3 = g_c[1];

    const int base = blockIdx.x * (G * DV) + tid;

    float4 xv = x4[base];

    #pragma unroll
    for (int g = 0; g < G; g++) {
        // three independent partial dots
        float p1 = xv.x * w1.x + xv.y * w1.y + xv.z * w1.z + xv.w * w1.w;
        float p2 = xv.x * w2.x + xv.y * w2.y + xv.z * w2.z + xv.w * w2.w;
        float p3 = xv.x * w3.x + xv.y * w3.y + xv.z * w3.z + xv.w * w3.w;

        // prefetch next row while reduction latency plays out
        float4 xnext;
        if (g + 1 < G) xnext = x4[base + (g + 1) * DV];

        // interleaved 3-chain butterfly reduce
        #pragma unroll
        for (int o = 16; o > 0; o >>= 1) {
            p1 += __shfl_xor_sync(0xFFFFFFFFu, p1, o);
            p2 += __shfl_xor_sync(0xFFFFFFFFu, p2, o);
            p3 += __shfl_xor_sync(0xFFFFFFFFu, p3, o);
        }

        if (lane == 0) red[g & 1][wid] = make_float4(p1, p2, p3, 0.f);
        __syncthreads();

        // every thread sums the 8 warp partials (broadcast LDS.128)
        float t1 = 0.f, t2 = 0.f, t3 = 0.f;
        #pragma unroll
        for (int i = 0; i < 8; i++) {
            float4 r = red[g & 1][i];
            t1 += r.x; t2 += r.y; t3 += r.z;
        }

        // scalar recurrence (redundant per thread, ~6 flops)
        const float s1 = 1.0f + t1;
        const float s2 = s1 + fmaf(s1, t2, c2);
        const float s3 = s2 + fmaf(s2, t3, c3);

        float4 o;
        o.x = fmaf(xv.x, s3, bs.x);
        o.y = fmaf(xv.y, s3, bs.y);
        o.z = fmaf(xv.z, s3, bs.z);
        o.w = fmaf(xv.w, s3, bs.w);
        out4[base + g * DV] = o;

        xv = xnext;
    }
}

extern "C" void kernel_launch(void* const* d_in, const int* in_sizes, int n_in,
                              void* d_out, int out_size)
{
    const float4* x4 = (const float4*)d_in[0];
    const float4* W4 = (const float4*)d_in[1];
    const float4* b4 = (const float4*)d_in[2];
    float4* out4 = (float4*)d_out;

    const int B = in_sizes[0] / D;   // 16384

    prologue_kernel<<<1, THREADS>>>(W4, b4);
    cross_layer_kernel<<<B / G, THREADS>>>(x4, W4, out4);
}

// round 4
// speedup vs baseline: 1.2796x; 1.2796x over previous
#include <cuda_runtime.h>

// CrossLayer DCN, closed form, warp-per-row:
//   t_l = <x, W_l>  (3 independent dots)
//   s1 = 1 + t1; s2 = s1 + (s1*t2 + c2); s3 = s2 + (s2*t3 + c3)
//   out = x * s3 + (b1+b2+b3)
// with c2 = <b1,W2>, c3 = <b1+b2,W3> computed once per block (staging phase).
//
// Block = 256 threads = 8 warps. W1/W2/W3/bsum staged in smem (16KB).
// Each warp processes G_W rows independently: lane owns 8 float4 of the row,
// dots reduce via one interleaved warp butterfly. No barriers in row loop.

#define D 1024
#define DV (D / 4)        // 256 float4 per row
#define THREADS 256
#define WARPS 8
#define G_W 4             // rows per warp
#define ROWS_PER_BLOCK (WARPS * G_W)   // 32

__global__ __launch_bounds__(THREADS)
void cross_layer_kernel(const float4* __restrict__ x4,
                        const float4* __restrict__ W4,
                        const float4* __restrict__ b4,
                        float4* __restrict__ out4)
{
    const int tid  = threadIdx.x;
    const int lane = tid & 31;
    const int wid  = tid >> 5;

    __shared__ float4 sW1[DV], sW2[DV], sW3[DV], sBs[DV];
    __shared__ float2 sRed[WARPS];

    // ---- staging: W, bsum -> smem; c2,c3 block-reduced ----
    {
        float4 w1 = __ldg(&W4[tid]);
        float4 w2 = __ldg(&W4[DV + tid]);
        float4 w3 = __ldg(&W4[2 * DV + tid]);
        float4 b1 = __ldg(&b4[tid]);
        float4 b2 = __ldg(&b4[DV + tid]);
        float4 b3 = __ldg(&b4[2 * DV + tid]);

        sW1[tid] = w1; sW2[tid] = w2; sW3[tid] = w3;
        float4 bs;
        bs.x = b1.x + b2.x + b3.x;
        bs.y = b1.y + b2.y + b3.y;
        bs.z = b1.z + b2.z + b3.z;
        bs.w = b1.w + b2.w + b3.w;
        sBs[tid] = bs;

        float p2 = b1.x * w2.x + b1.y * w2.y + b1.z * w2.z + b1.w * w2.w;
        float b12x = b1.x + b2.x, b12y = b1.y + b2.y;
        float b12z = b1.z + b2.z, b12w = b1.w + b2.w;
        float p3 = b12x * w3.x + b12y * w3.y + b12z * w3.z + b12w * w3.w;

        #pragma unroll
        for (int o = 16; o > 0; o >>= 1) {
            p2 += __shfl_xor_sync(0xFFFFFFFFu, p2, o);
            p3 += __shfl_xor_sync(0xFFFFFFFFu, p3, o);
        }
        if (lane == 0) sRed[wid] = make_float2(p2, p3);
    }
    __syncthreads();

    float c2 = 0.f, c3 = 0.f;
    #pragma unroll
    for (int i = 0; i < WARPS; i++) { c2 += sRed[i].x; c3 += sRed[i].y; }

    // ---- row loop: warp-independent, no barriers ----
    const int row0 = blockIdx.x * ROWS_PER_BLOCK + wid * G_W;

    #pragma unroll
    for (int g = 0; g < G_W; g++) {
        const int base = (row0 + g) * DV + lane;

        float4 xv[8];
        #pragma unroll
        for (int i = 0; i < 8; i++)
            xv[i] = __ldcs(&x4[base + i * 32]);

        float p1 = 0.f, p2 = 0.f, p3 = 0.f;
        #pragma unroll
        for (int i = 0; i < 8; i++) {
            const int idx = i * 32 + lane;
            float4 w1 = sW1[idx];
            p1 += xv[i].x * w1.x + xv[i].y * w1.y + xv[i].z * w1.z + xv[i].w * w1.w;
            float4 w2 = sW2[idx];
            p2 += xv[i].x * w2.x + xv[i].y * w2.y + xv[i].z * w2.z + xv[i].w * w2.w;
            float4 w3 = sW3[idx];
            p3 += xv[i].x * w3.x + xv[i].y * w3.y + xv[i].z * w3.z + xv[i].w * w3.w;
        }

        // interleaved butterfly: all lanes end with full sums
        #pragma unroll
        for (int o = 16; o > 0; o >>= 1) {
            p1 += __shfl_xor_sync(0xFFFFFFFFu, p1, o);
            p2 += __shfl_xor_sync(0xFFFFFFFFu, p2, o);
            p3 += __shfl_xor_sync(0xFFFFFFFFu, p3, o);
        }

        const float s1 = 1.0f + p1;
        const float s2 = s1 + fmaf(s1, p2, c2);
        const float s3 = s2 + fmaf(s2, p3, c3);

        #pragma unroll
        for (int i = 0; i < 8; i++) {
            const float4 bs = sBs[i * 32 + lane];
            float4 o;
            o.x = fmaf(xv[i].x, s3, bs.x);
            o.y = fmaf(xv[i].y, s3, bs.y);
            o.z = fmaf(xv[i].z, s3, bs.z);
            o.w = fmaf(xv[i].w, s3, bs.w);
            __stcs(&out4[base + i * 32], o);
        }
    }
}

extern "C" void kernel_launch(void* const* d_in, const int* in_sizes, int n_in,
                              void* d_out, int out_size)
{
    const float4* x4 = (const float4*)d_in[0];
    const float4* W4 = (const float4*)d_in[1];
    const float4* b4 = (const float4*)d_in[2];
    float4* out4 = (float4*)d_out;

    const int B = in_sizes[0] / D;   // 16384

    cross_layer_kernel<<<B / ROWS_PER_BLOCK, THREADS>>>(x4, W4, b4, out4);
}

// round 5
// speedup vs baseline: 1.4753x; 1.1530x over previous
#include <cuda_runtime.h>

// CrossLayer DCN, closed form, warp-per-row:
//   t_l = <x, W_l>;  s1 = 1+t1; s2 = s1 + (s1*t2 + c2); s3 = s2 + (s2*t3 + c3)
//   out = x * s3 + (b1+b2+b3);  c2 = <b1,W2>, c3 = <b1+b2,W3>
//
// Block = 256 threads = 8 warps; W/bsum staged in smem (16KB); each warp
// processes rows independently (no barriers in row loop). g-loop kept
// rolled (#pragma unroll 1) so W stays in smem, not hoisted into registers;
// launch_bounds(256,3) pins 3 blocks/SM for latency hiding.

#define D 1024
#define DV (D / 4)
#define THREADS 256
#define WARPS 8
#define G_W 2
#define ROWS_PER_BLOCK (WARPS * G_W)   // 16

__global__ __launch_bounds__(THREADS, 3)
void cross_layer_kernel(const float4* __restrict__ x4,
                        const float4* __restrict__ W4,
                        const float4* __restrict__ b4,
                        float4* __restrict__ out4)
{
    const int tid  = threadIdx.x;
    const int lane = tid & 31;
    const int wid  = tid >> 5;

    __shared__ float4 sW1[DV], sW2[DV], sW3[DV], sBs[DV];
    __shared__ float2 sRed[WARPS];

    // ---- staging: W, bsum -> smem; c2,c3 block-reduced ----
    {
        float4 w1 = __ldg(&W4[tid]);
        float4 w2 = __ldg(&W4[DV + tid]);
        float4 w3 = __ldg(&W4[2 * DV + tid]);
        float4 b1 = __ldg(&b4[tid]);
        float4 b2 = __ldg(&b4[DV + tid]);
        float4 b3 = __ldg(&b4[2 * DV + tid]);

        sW1[tid] = w1; sW2[tid] = w2; sW3[tid] = w3;
        float4 bs;
        bs.x = b1.x + b2.x + b3.x;
        bs.y = b1.y + b2.y + b3.y;
        bs.z = b1.z + b2.z + b3.z;
        bs.w = b1.w + b2.w + b3.w;
        sBs[tid] = bs;

        float p2 = b1.x * w2.x + b1.y * w2.y + b1.z * w2.z + b1.w * w2.w;
        float b12x = b1.x + b2.x, b12y = b1.y + b2.y;
        float b12z = b1.z + b2.z, b12w = b1.w + b2.w;
        float p3 = b12x * w3.x + b12y * w3.y + b12z * w3.z + b12w * w3.w;

        #pragma unroll
        for (int o = 16; o > 0; o >>= 1) {
            p2 += __shfl_xor_sync(0xFFFFFFFFu, p2, o);
            p3 += __shfl_xor_sync(0xFFFFFFFFu, p3, o);
        }
        if (lane == 0) sRed[wid] = make_float2(p2, p3);
    }
    __syncthreads();

    float c2 = 0.f, c3 = 0.f;
    #pragma unroll
    for (int i = 0; i < WARPS; i++) { c2 += sRed[i].x; c3 += sRed[i].y; }

    // ---- row loop: warp-independent, no barriers, W stays in smem ----
    const int row0 = blockIdx.x * ROWS_PER_BLOCK + wid * G_W;

    #pragma unroll 1
    for (int g = 0; g < G_W; g++) {
        const int base = (row0 + g) * DV + lane;

        float4 xv[8];
        #pragma unroll
        for (int i = 0; i < 8; i++)
            xv[i] = __ldcs(&x4[base + i * 32]);

        float p1 = 0.f, p2 = 0.f, p3 = 0.f;
        #pragma unroll
        for (int i = 0; i < 8; i++) {
            const int idx = i * 32 + lane;
            float4 w1 = sW1[idx];
            p1 += xv[i].x * w1.x + xv[i].y * w1.y + xv[i].z * w1.z + xv[i].w * w1.w;
            float4 w2 = sW2[idx];
            p2 += xv[i].x * w2.x + xv[i].y * w2.y + xv[i].z * w2.z + xv[i].w * w2.w;
            float4 w3 = sW3[idx];
            p3 += xv[i].x * w3.x + xv[i].y * w3.y + xv[i].z * w3.z + xv[i].w * w3.w;
        }

        // interleaved butterfly: all lanes end with full sums
        #pragma unroll
        for (int o = 16; o > 0; o >>= 1) {
            p1 += __shfl_xor_sync(0xFFFFFFFFu, p1, o);
            p2 += __shfl_xor_sync(0xFFFFFFFFu, p2, o);
            p3 += __shfl_xor_sync(0xFFFFFFFFu, p3, o);
        }

        const float s1 = 1.0f + p1;
        const float s2 = s1 + fmaf(s1, p2, c2);
        const float s3 = s2 + fmaf(s2, p3, c3);

        #pragma unroll
        for (int i = 0; i < 8; i++) {
            const float4 bs = sBs[i * 32 + lane];
            float4 o;
            o.x = fmaf(xv[i].x, s3, bs.x);
            o.y = fmaf(xv[i].y, s3, bs.y);
            o.z = fmaf(xv[i].z, s3, bs.z);
            o.w = fmaf(xv[i].w, s3, bs.w);
            __stcs(&out4[base + i * 32], o);
        }
    }
}

extern "C" void kernel_launch(void* const* d_in, const int* in_sizes, int n_in,
                              void* d_out, int out_size)
{
    const float4* x4 = (const float4*)d_in[0];
    const float4* W4 = (const float4*)d_in[1];
    const float4* b4 = (const float4*)d_in[2];
    float4* out4 = (float4*)d_out;

    const int B = in_sizes[0] / D;   // 16384

    cross_layer_kernel<<<B / ROWS_PER_BLOCK, THREADS>>>(x4, W4, b4, out4);
}

// round 6
// speedup vs baseline: 1.4904x; 1.0102x over previous
#include <cuda_runtime.h>

// CrossLayer DCN, closed form, warp-per-row:
//   t_l = <x, W_l>;  s1 = 1+t1; s2 = s1 + (s1*t2 + c2); s3 = s2 + (s2*t3 + c3)
//   out = x * s3 + (b1+b2+b3);  c2 = <b1,W2>, c3 = <b1+b2,W3>
//
// Block = 256 threads = 8 warps; W/bsum staged in smem (16KB); each warp
// processes rows independently (no barriers in row loop). g-loop rolled so
// W stays in smem; launch_bounds(256,4) caps regs at 64 -> 4 blocks/SM
// (50% occupancy) to hide the LDG + butterfly latency chain.

#define D 1024
#define DV (D / 4)
#define THREADS 256
#define WARPS 8
#define G_W 2
#define ROWS_PER_BLOCK (WARPS * G_W)   // 16

__global__ __launch_bounds__(THREADS, 4)
void cross_layer_kernel(const float4* __restrict__ x4,
                        const float4* __restrict__ W4,
                        const float4* __restrict__ b4,
                        float4* __restrict__ out4)
{
    const int tid  = threadIdx.x;
    const int lane = tid & 31;
    const int wid  = tid >> 5;

    __shared__ float4 sW1[DV], sW2[DV], sW3[DV], sBs[DV];
    __shared__ float2 sRed[WARPS];

    // ---- staging: W, bsum -> smem; c2,c3 block-reduced ----
    {
        float4 w1 = __ldg(&W4[tid]);
        float4 w2 = __ldg(&W4[DV + tid]);
        float4 w3 = __ldg(&W4[2 * DV + tid]);
        float4 b1 = __ldg(&b4[tid]);
        float4 b2 = __ldg(&b4[DV + tid]);
        float4 b3 = __ldg(&b4[2 * DV + tid]);

        sW1[tid] = w1; sW2[tid] = w2; sW3[tid] = w3;
        float4 bs;
        bs.x = b1.x + b2.x + b3.x;
        bs.y = b1.y + b2.y + b3.y;
        bs.z = b1.z + b2.z + b3.z;
        bs.w = b1.w + b2.w + b3.w;
        sBs[tid] = bs;

        float p2 = b1.x * w2.x + b1.y * w2.y + b1.z * w2.z + b1.w * w2.w;
        float b12x = b1.x + b2.x, b12y = b1.y + b2.y;
        float b12z = b1.z + b2.z, b12w = b1.w + b2.w;
        float p3 = b12x * w3.x + b12y * w3.y + b12z * w3.z + b12w * w3.w;

        #pragma unroll
        for (int o = 16; o > 0; o >>= 1) {
            p2 += __shfl_xor_sync(0xFFFFFFFFu, p2, o);
            p3 += __shfl_xor_sync(0xFFFFFFFFu, p3, o);
        }
        if (lane == 0) sRed[wid] = make_float2(p2, p3);
    }
    __syncthreads();

    float c2 = 0.f, c3 = 0.f;
    #pragma unroll
    for (int i = 0; i < WARPS; i++) { c2 += sRed[i].x; c3 += sRed[i].y; }

    // ---- row loop: warp-independent, no barriers, W stays in smem ----
    const int row0 = blockIdx.x * ROWS_PER_BLOCK + wid * G_W;

    #pragma unroll 1
    for (int g = 0; g < G_W; g++) {
        const int base = (row0 + g) * DV + lane;

        float4 xv[8];
        #pragma unroll
        for (int i = 0; i < 8; i++)
            xv[i] = __ldcs(&x4[base + i * 32]);

        float p1 = 0.f, p2 = 0.f, p3 = 0.f;
        #pragma unroll
        for (int i = 0; i < 8; i++) {
            const int idx = i * 32 + lane;
            float4 w1 = sW1[idx];
            p1 += xv[i].x * w1.x + xv[i].y * w1.y + xv[i].z * w1.z + xv[i].w * w1.w;
            float4 w2 = sW2[idx];
            p2 += xv[i].x * w2.x + xv[i].y * w2.y + xv[i].z * w2.z + xv[i].w * w2.w;
            float4 w3 = sW3[idx];
            p3 += xv[i].x * w3.x + xv[i].y * w3.y + xv[i].z * w3.z + xv[i].w * w3.w;
        }

        // interleaved butterfly: all lanes end with full sums
        #pragma unroll
        for (int o = 16; o > 0; o >>= 1) {
            p1 += __shfl_xor_sync(0xFFFFFFFFu, p1, o);
            p2 += __shfl_xor_sync(0xFFFFFFFFu, p2, o);
            p3 += __shfl_xor_sync(0xFFFFFFFFu, p3, o);
        }

        const float s1 = 1.0f + p1;
        const float s2 = s1 + fmaf(s1, p2, c2);
        const float s3 = s2 + fmaf(s2, p3, c3);

        #pragma unroll
        for (int i = 0; i < 8; i++) {
            const float4 bs = sBs[i * 32 + lane];
            float4 o;
            o.x = fmaf(xv[i].x, s3, bs.x);
            o.y = fmaf(xv[i].y, s3, bs.y);
            o.z = fmaf(xv[i].z, s3, bs.z);
            o.w = fmaf(xv[i].w, s3, bs.w);
            __stcs(&out4[base + i * 32], o);
        }
    }
}

extern "C" void kernel_launch(void* const* d_in, const int* in_sizes, int n_in,
                              void* d_out, int out_size)
{
    const float4* x4 = (const float4*)d_in[0];
    const float4* W4 = (const float4*)d_in[1];
    const float4* b4 = (const float4*)d_in[2];
    float4* out4 = (float4*)d_out;

    const int B = in_sizes[0] / D;   // 16384

    cross_layer_kernel<<<B / ROWS_PER_BLOCK, THREADS>>>(x4, W4, b4, out4);
}